// round 5
// baseline (speedup 1.0000x reference)
#include <cuda_runtime.h>

#define NB    32
#define HWD   3136
#define CD    256
#define DIM   802816          // 56*56*256
#define KSEL  160564u         // ceil(0.2 * 802816)
#define CUTF  0.70f           // conservative cut; P(x>=0.70)≈0.242 >> 0.20003 (fallback covers misses)

// ---------------- static device scratch ----------------
__device__ unsigned int g_cnt[NB];
__device__ unsigned int g_flag;
__device__ unsigned int g_h1[NB][2048];       // round-1 histogram (bits [31:21])
__device__ unsigned int g_thresh[NB];         // kth-largest bit pattern (mode-dependent encoding)
__device__ unsigned int g_scratch[NB][DIM];   // candidate buffer (sized for fallback = all)

// order-preserving float->uint (only used on fallback path + mask fallback compare)
__device__ __forceinline__ unsigned int f2u(float f) {
    unsigned int b = __float_as_uint(f);
    return b ^ (((int)b >> 31) | 0x80000000u);
}

// ---------------- zero counters + round-1 histogram ----------------
__global__ void k_zero() {
    int i = blockIdx.x * blockDim.x + threadIdx.x;     // 64*1024 = 65536 = NB*2048
    ((unsigned int*)g_h1)[i] = 0u;
    if (i < NB) g_cnt[i] = 0u;
    if (i == NB) g_flag = 0u;
}

// ---------------- single-pass cut compaction (raw positive float bits) ----------------
__global__ void k_compact_cut(const float* __restrict__ x) {
    __shared__ unsigned int s_w[8], s_woff[8], s_base;
    int b = blockIdx.y;
    int t = threadIdx.x, lane = t & 31, wid = t >> 5;
    const float4* xp = (const float4*)(x + (size_t)b * DIM) + (size_t)blockIdx.x * 1024;

    float4 v0 = xp[t], v1 = xp[t + 256], v2 = xp[t + 512], v3 = xp[t + 768];
    float f[16] = {v0.x, v0.y, v0.z, v0.w, v1.x, v1.y, v1.z, v1.w,
                   v2.x, v2.y, v2.z, v2.w, v3.x, v3.y, v3.z, v3.w};

    unsigned int c = 0;
    #pragma unroll
    for (int j = 0; j < 16; j++) c += (f[j] >= CUTF);

    // warp inclusive scan of per-thread counts
    unsigned int incl = c;
    #pragma unroll
    for (int o = 1; o < 32; o <<= 1) {
        unsigned int p = __shfl_up_sync(0xffffffffu, incl, o);
        if (lane >= o) incl += p;
    }
    if (lane == 31) s_w[wid] = incl;
    __syncthreads();
    if (t == 0) {
        unsigned int run = 0;
        #pragma unroll
        for (int w = 0; w < 8; w++) { s_woff[w] = run; run += s_w[w]; }
        s_base = run ? atomicAdd(&g_cnt[b], run) : 0u;
    }
    __syncthreads();

    unsigned int idx = s_base + s_woff[wid] + (incl - c);
    unsigned int* dst = g_scratch[b];
    #pragma unroll
    for (int j = 0; j < 16; j++)
        if (f[j] >= CUTF) dst[idx++] = __float_as_uint(f[j]);  // positive: raw bits monotonic
}

// ---------------- guard: arm fallback if cut was too aggressive ----------------
__global__ void k_checkflag() {
    int t = threadIdx.x;   // 32 threads
    unsigned int bad = __ballot_sync(0xffffffffu, g_cnt[t] < KSEL);
    if (bad) {
        if (t == 0) g_flag = 1u;
        g_cnt[t] = DIM;    // fallback uses all elements, identity-indexed
    }
}

// ---------------- fallback: full f2u recompaction (early-exits when unarmed) ----------------
__global__ void k_fallback(const float* __restrict__ x) {
    if (g_flag == 0u) return;
    int b = blockIdx.y;
    size_t off = (size_t)blockIdx.x * 4096;
    const float* xb = x + (size_t)b * DIM + off;
    unsigned int* dst = g_scratch[b] + off;
    for (int i = threadIdx.x; i < 4096; i += 256) dst[i] = f2u(xb[i]);
}

// ---------------- select round 1: multi-block histogram of bits [31:21] ----------------
__global__ void k_sel_hist1() {
    __shared__ unsigned int h[2048];
    int b = blockIdx.y;
    for (int i = threadIdx.x; i < 2048; i += 256) h[i] = 0u;
    __syncthreads();
    unsigned int n = g_cnt[b];
    unsigned int slice = (n + 7u) >> 3;
    unsigned int s0 = blockIdx.x * slice;
    unsigned int s1 = min(s0 + slice, n);
    const unsigned int* sp = g_scratch[b];
    for (unsigned int i = s0 + threadIdx.x; i < s1; i += 256)
        atomicAdd(&h[sp[i] >> 21], 1u);
    __syncthreads();
    for (int i = threadIdx.x; i < 2048; i += 256) {
        unsigned int c = h[i];
        if (c) atomicAdd(&g_h1[b][i], c);
    }
}

// ---------------- select rounds 1(scan)+2+3: exact kth pattern ----------------
__global__ void k_sel_rest() {
    __shared__ unsigned int h[2048];
    __shared__ unsigned int part[1024];
    __shared__ unsigned int s_bin, s_kr;
    int b = blockIdx.x, t = threadIdx.x;     // 1024 threads
    unsigned int n = g_cnt[b];
    const unsigned int* sp = g_scratch[b];
    unsigned int kr = KSEL;

    // ---- round 1: scan global histogram (2048 bins, descending) ----
    h[t] = g_h1[b][t]; h[t + 1024] = g_h1[b][t + 1024];
    __syncthreads();
    {
        unsigned int loc0 = h[2047 - 2 * t], loc1 = h[2046 - 2 * t];
        unsigned int s = loc0 + loc1;
        part[t] = s; __syncthreads();
        for (int o = 1; o < 1024; o <<= 1) {
            unsigned int a = (t >= o) ? part[t - o] : 0u;
            __syncthreads(); part[t] += a; __syncthreads();
        }
        unsigned int incl = part[t], excl = incl - s;
        if (excl < kr && incl >= kr) {
            if (excl + loc0 >= kr) { s_bin = 2047 - 2 * t; s_kr = kr - excl; }
            else                   { s_bin = 2046 - 2 * t; s_kr = kr - excl - loc0; }
        }
        __syncthreads();
    }
    unsigned int b1 = s_bin; kr = s_kr;
    __syncthreads();

    // ---- round 2: bits [20:10] among b1-matching ----
    h[t] = 0u; h[t + 1024] = 0u;
    __syncthreads();
    for (unsigned int i = t; i < n; i += 1024) {
        unsigned int u = sp[i];
        if ((u >> 21) == b1) atomicAdd(&h[(u >> 10) & 2047u], 1u);
    }
    __syncthreads();
    {
        unsigned int loc0 = h[2047 - 2 * t], loc1 = h[2046 - 2 * t];
        unsigned int s = loc0 + loc1;
        part[t] = s; __syncthreads();
        for (int o = 1; o < 1024; o <<= 1) {
            unsigned int a = (t >= o) ? part[t - o] : 0u;
            __syncthreads(); part[t] += a; __syncthreads();
        }
        unsigned int incl = part[t], excl = incl - s;
        if (excl < kr && incl >= kr) {
            if (excl + loc0 >= kr) { s_bin = 2047 - 2 * t; s_kr = kr - excl; }
            else                   { s_bin = 2046 - 2 * t; s_kr = kr - excl - loc0; }
        }
        __syncthreads();
    }
    unsigned int b2 = s_bin; kr = s_kr;
    __syncthreads();

    // ---- round 3: bits [9:0] among (b1,b2)-matching ----
    h[t] = 0u;
    __syncthreads();
    unsigned int top = (b1 << 11) | b2;
    for (unsigned int i = t; i < n; i += 1024) {
        unsigned int u = sp[i];
        if ((u >> 10) == top) atomicAdd(&h[u & 1023u], 1u);
    }
    __syncthreads();
    {
        unsigned int s = h[1023 - t];
        part[t] = s; __syncthreads();
        for (int o = 1; o < 1024; o <<= 1) {
            unsigned int a = (t >= o) ? part[t - o] : 0u;
            __syncthreads(); part[t] += a; __syncthreads();
        }
        unsigned int incl = part[t], excl = incl - s;
        if (excl < kr && incl >= kr)
            g_thresh[b] = (b1 << 21) | (b2 << 10) | (unsigned int)(1023 - t);
    }
}

// ---------------- threshold + NHWC->NCHW-flatten transpose ----------------
__global__ void k_mask(const float* __restrict__ x, float* __restrict__ out) {
    __shared__ float tile[32][33];
    int b = blockIdx.z;
    unsigned int uth = g_thresh[b];
    bool fb = (g_flag != 0u);
    float tf = __uint_as_float(uth);
    const float* xb = x + (size_t)b * DIM;
    float* ob = out + (size_t)b * DIM;
    int hw0 = blockIdx.x * 32;
    int c0  = blockIdx.y * 32;
    int tx = threadIdx.x, ty = threadIdx.y;

    #pragma unroll
    for (int i = 0; i < 32; i += 8) {
        float v = xb[(size_t)(hw0 + ty + i) * CD + (c0 + tx)];
        bool keep = fb ? (f2u(v) >= uth) : (v >= tf);
        tile[ty + i][tx] = keep ? v : 0.0f;
    }
    __syncthreads();
    #pragma unroll
    for (int i = 0; i < 32; i += 8) {
        ob[(size_t)(c0 + ty + i) * HWD + (hw0 + tx)] = tile[tx][ty + i];
    }
}

// ---------------- launch ----------------
extern "C" void kernel_launch(void* const* d_in, const int* in_sizes, int n_in,
                              void* d_out, int out_size) {
    const float* x = (const float*)d_in[0];
    float* out = (float*)d_out;

    k_zero<<<64, 1024>>>();
    k_compact_cut<<<dim3(196, NB), 256>>>(x);     // 196*4096 = 802816 exactly
    k_checkflag<<<1, 32>>>();
    k_fallback<<<dim3(196, NB), 256>>>(x);
    k_sel_hist1<<<dim3(8, NB), 256>>>();
    k_sel_rest<<<NB, 1024>>>();
    k_mask<<<dim3(HWD / 32, CD / 32, NB), dim3(32, 8)>>>(x, out);
}

// round 6
// speedup vs baseline: 1.1287x; 1.1287x over previous
#include <cuda_runtime.h>

#define NB    32
#define HWD   3136
#define CD    256
#define DIM   802816          // 56*56*256
#define KSEL  160564u         // ceil(0.2 * 802816)
#define CUTF  0.70f           // conservative cut; P(x>=0.70)~0.242 >> 0.20003; guard covers misses

// ---------------- static device scratch ----------------
__device__ unsigned int g_cnt[NB];
__device__ unsigned int g_h1[NB][2048];       // round-1 histogram (bits [31:21])
__device__ unsigned int g_thresh[NB];         // kth-largest bit pattern (encoding per path)
__device__ unsigned int g_scratch[NB][DIM];   // candidate buffer

// order-preserving float->uint (fallback path only)
__device__ __forceinline__ unsigned int f2u(float f) {
    unsigned int b = __float_as_uint(f);
    return b ^ (((int)b >> 31) | 0x80000000u);
}

// shfl-based inclusive scan over 1024 threads (2 barriers)
__device__ __forceinline__ unsigned int blockscan1024(unsigned int s, unsigned int* s_warp,
                                                      int lane, int wid) {
    unsigned int incl = s;
    #pragma unroll
    for (int o = 1; o < 32; o <<= 1) {
        unsigned int p = __shfl_up_sync(0xffffffffu, incl, o);
        if (lane >= o) incl += p;
    }
    if (lane == 31) s_warp[wid] = incl;
    __syncthreads();
    if (wid == 0) {
        unsigned int w = s_warp[lane];
        #pragma unroll
        for (int o = 1; o < 32; o <<= 1) {
            unsigned int p = __shfl_up_sync(0xffffffffu, w, o);
            if (lane >= o) w += p;
        }
        s_warp[lane] = w;
    }
    __syncthreads();
    return incl + (wid ? s_warp[wid - 1] : 0u);
}

// ---------------- zero counters + round-1 histogram ----------------
__global__ void k_zero() {
    int i = blockIdx.x * blockDim.x + threadIdx.x;   // 64*1024 = NB*2048
    ((unsigned int*)g_h1)[i] = 0u;
    if (i < NB) g_cnt[i] = 0u;
}

// ---------------- single-pass cut compaction, smem-staged coalesced writes ----------------
__global__ void k_compact_cut(const float* __restrict__ x) {
    __shared__ unsigned int s_buf[4096];
    __shared__ unsigned int s_w[8], s_woff[8], s_base, s_tot;
    int b = blockIdx.y;
    int t = threadIdx.x, lane = t & 31, wid = t >> 5;
    const float4* xp = (const float4*)(x + (size_t)b * DIM) + (size_t)blockIdx.x * 1024;

    float4 v0 = xp[t], v1 = xp[t + 256], v2 = xp[t + 512], v3 = xp[t + 768];
    float f[16] = {v0.x, v0.y, v0.z, v0.w, v1.x, v1.y, v1.z, v1.w,
                   v2.x, v2.y, v2.z, v2.w, v3.x, v3.y, v3.z, v3.w};

    unsigned int c = 0;
    #pragma unroll
    for (int j = 0; j < 16; j++) c += (f[j] >= CUTF);

    unsigned int incl = c;
    #pragma unroll
    for (int o = 1; o < 32; o <<= 1) {
        unsigned int p = __shfl_up_sync(0xffffffffu, incl, o);
        if (lane >= o) incl += p;
    }
    if (lane == 31) s_w[wid] = incl;
    __syncthreads();
    if (t == 0) {
        unsigned int run = 0;
        #pragma unroll
        for (int w = 0; w < 8; w++) { s_woff[w] = run; run += s_w[w]; }
        s_tot = run;
        s_base = run ? atomicAdd(&g_cnt[b], run) : 0u;
    }
    __syncthreads();

    unsigned int idx = s_woff[wid] + (incl - c);
    #pragma unroll
    for (int j = 0; j < 16; j++)
        if (f[j] >= CUTF) s_buf[idx++] = __float_as_uint(f[j]);  // positive: raw bits monotonic
    __syncthreads();

    unsigned int tot = s_tot, base = s_base;
    unsigned int* dst = g_scratch[b];
    for (unsigned int i = t; i < tot; i += 256) dst[base + i] = s_buf[i];
}

// ---------------- select round 1: multi-block histogram of bits [31:21] ----------------
__global__ void k_sel_hist1(const float* __restrict__ x) {
    __shared__ unsigned int h[2048];
    int b = blockIdx.y, t = threadIdx.x;
    for (int i = t; i < 2048; i += 256) h[i] = 0u;
    __syncthreads();

    unsigned int n = g_cnt[b];
    if (n >= KSEL) {
        const unsigned int* sp = g_scratch[b];
        unsigned int slice = ((n + 31u) >> 5) << 2;          // mult of 4; 8*slice >= n
        unsigned int s0 = blockIdx.x * slice;
        unsigned int s1 = min(s0 + slice, n);
        unsigned int s1v = s1 & ~3u;
        for (unsigned int i = s0 + 4u * t; i + 3u < s1v + 4u && i + 3u < s1; i += 1024u) {
            uint4 u = *(const uint4*)(sp + i);
            atomicAdd(&h[u.x >> 21], 1u);
            atomicAdd(&h[u.y >> 21], 1u);
            atomicAdd(&h[u.z >> 21], 1u);
            atomicAdd(&h[u.w >> 21], 1u);
        }
        for (unsigned int i = (s1v > s0 ? s1v : s0) + t; i < s1; i += 256)
            atomicAdd(&h[sp[i] >> 21], 1u);
    } else {
        // fallback: histogram full sample with f2u encoding
        const float* xb = x + (size_t)b * DIM;
        unsigned int slice = DIM / 8;                         // 100352, mult of 4
        unsigned int s0 = blockIdx.x * slice;
        const float4* xp = (const float4*)(xb + s0);
        for (unsigned int i = t; i < slice / 4; i += 256) {
            float4 v = xp[i];
            atomicAdd(&h[f2u(v.x) >> 21], 1u);
            atomicAdd(&h[f2u(v.y) >> 21], 1u);
            atomicAdd(&h[f2u(v.z) >> 21], 1u);
            atomicAdd(&h[f2u(v.w) >> 21], 1u);
        }
    }
    __syncthreads();
    for (int i = t; i < 2048; i += 256) {
        unsigned int c = h[i];
        if (c) atomicAdd(&g_h1[b][i], c);
    }
}

// ---------------- select rounds 1(scan)+2+3: exact kth pattern ----------------
__global__ void k_sel_rest(const float* __restrict__ x) {
    __shared__ unsigned int h[2048];
    __shared__ unsigned int s_warp[32];
    __shared__ unsigned int s_bin, s_kr;
    int b = blockIdx.x, t = threadIdx.x;     // 1024 threads
    int lane = t & 31, wid = t >> 5;
    unsigned int n = g_cnt[b];
    bool fb = (n < KSEL);
    if (fb) n = DIM;
    const unsigned int* sp = g_scratch[b];
    const float* xb = x + (size_t)b * DIM;
    unsigned int kr = KSEL;

    // ---- round 1: scan global histogram (2048 bins, descending, 2/thread) ----
    h[t] = g_h1[b][t]; h[t + 1024] = g_h1[b][t + 1024];
    __syncthreads();
    {
        unsigned int loc0 = h[2047 - 2 * t], loc1 = h[2046 - 2 * t];
        unsigned int s = loc0 + loc1;
        unsigned int incl = blockscan1024(s, s_warp, lane, wid);
        unsigned int excl = incl - s;
        if (excl < kr && incl >= kr) {
            if (excl + loc0 >= kr) { s_bin = 2047 - 2 * t; s_kr = kr - excl; }
            else                   { s_bin = 2046 - 2 * t; s_kr = kr - excl - loc0; }
        }
        __syncthreads();
    }
    unsigned int b1 = s_bin; kr = s_kr;
    __syncthreads();

    // ---- round 2: bits [20:10] among b1-matching ----
    h[t] = 0u; h[t + 1024] = 0u;
    __syncthreads();
    if (!fb) {
        unsigned int nv = n & ~3u;
        for (unsigned int i = 4u * t; i < nv; i += 4096u) {
            uint4 u = *(const uint4*)(sp + i);
            if ((u.x >> 21) == b1) atomicAdd(&h[(u.x >> 10) & 2047u], 1u);
            if ((u.y >> 21) == b1) atomicAdd(&h[(u.y >> 10) & 2047u], 1u);
            if ((u.z >> 21) == b1) atomicAdd(&h[(u.z >> 10) & 2047u], 1u);
            if ((u.w >> 21) == b1) atomicAdd(&h[(u.w >> 10) & 2047u], 1u);
        }
        for (unsigned int i = nv + t; i < n; i += 1024) {
            unsigned int u = sp[i];
            if ((u >> 21) == b1) atomicAdd(&h[(u >> 10) & 2047u], 1u);
        }
    } else {
        for (unsigned int i = t; i < n; i += 1024) {
            unsigned int u = f2u(xb[i]);
            if ((u >> 21) == b1) atomicAdd(&h[(u >> 10) & 2047u], 1u);
        }
    }
    __syncthreads();
    {
        unsigned int loc0 = h[2047 - 2 * t], loc1 = h[2046 - 2 * t];
        unsigned int s = loc0 + loc1;
        unsigned int incl = blockscan1024(s, s_warp, lane, wid);
        unsigned int excl = incl - s;
        if (excl < kr && incl >= kr) {
            if (excl + loc0 >= kr) { s_bin = 2047 - 2 * t; s_kr = kr - excl; }
            else                   { s_bin = 2046 - 2 * t; s_kr = kr - excl - loc0; }
        }
        __syncthreads();
    }
    unsigned int b2 = s_bin; kr = s_kr;
    __syncthreads();

    // ---- round 3: bits [9:0] among (b1,b2)-matching ----
    h[t] = 0u;
    __syncthreads();
    unsigned int top = (b1 << 11) | b2;
    if (!fb) {
        unsigned int nv = n & ~3u;
        for (unsigned int i = 4u * t; i < nv; i += 4096u) {
            uint4 u = *(const uint4*)(sp + i);
            if ((u.x >> 10) == top) atomicAdd(&h[u.x & 1023u], 1u);
            if ((u.y >> 10) == top) atomicAdd(&h[u.y & 1023u], 1u);
            if ((u.z >> 10) == top) atomicAdd(&h[u.z & 1023u], 1u);
            if ((u.w >> 10) == top) atomicAdd(&h[u.w & 1023u], 1u);
        }
        for (unsigned int i = nv + t; i < n; i += 1024) {
            unsigned int u = sp[i];
            if ((u >> 10) == top) atomicAdd(&h[u & 1023u], 1u);
        }
    } else {
        for (unsigned int i = t; i < n; i += 1024) {
            unsigned int u = f2u(xb[i]);
            if ((u >> 10) == top) atomicAdd(&h[u & 1023u], 1u);
        }
    }
    __syncthreads();
    {
        unsigned int s = (t < 1024) ? h[1023 - t] : 0u;
        unsigned int incl = blockscan1024(s, s_warp, lane, wid);
        unsigned int excl = incl - s;
        if (excl < kr && incl >= kr)
            g_thresh[b] = (b1 << 21) | (b2 << 10) | (unsigned int)(1023 - t);
    }
}

// ---------------- threshold + NHWC->NCHW-flatten transpose (128-bit both sides) ----------------
__global__ void k_mask(const float* __restrict__ x, float* __restrict__ out) {
    __shared__ float tile[32][33];         // [c_local][hw_local]
    int b = blockIdx.z;
    unsigned int uth = g_thresh[b];
    bool fb = (g_cnt[b] < KSEL);
    float tf = __uint_as_float(uth);
    const float* xb = x + (size_t)b * DIM;
    float* ob = out + (size_t)b * DIM;
    int hw0 = blockIdx.x * 32;
    int c0  = blockIdx.y * 32;
    int tx = threadIdx.x;                  // 0..7  (quad index)
    int ty = threadIdx.y;                  // 0..31

    // load: float4 along C
    float4 v = *(const float4*)(xb + (size_t)(hw0 + ty) * CD + (c0 + 4 * tx));
    float r[4] = {v.x, v.y, v.z, v.w};
    #pragma unroll
    for (int q = 0; q < 4; q++) {
        bool keep = fb ? (f2u(r[q]) >= uth) : (r[q] >= tf);
        tile[4 * tx + q][ty] = keep ? r[q] : 0.0f;
    }
    __syncthreads();

    // store: float4 along HW
    float4 w;
    w.x = tile[ty][4 * tx];
    w.y = tile[ty][4 * tx + 1];
    w.z = tile[ty][4 * tx + 2];
    w.w = tile[ty][4 * tx + 3];
    *(float4*)(ob + (size_t)(c0 + ty) * HWD + (hw0 + 4 * tx)) = w;
}

// ---------------- launch ----------------
extern "C" void kernel_launch(void* const* d_in, const int* in_sizes, int n_in,
                              void* d_out, int out_size) {
    const float* x = (const float*)d_in[0];
    float* out = (float*)d_out;

    k_zero<<<64, 1024>>>();
    k_compact_cut<<<dim3(196, NB), 256>>>(x);         // 196*4096 = 802816 exactly
    k_sel_hist1<<<dim3(8, NB), 256>>>(x);
    k_sel_rest<<<NB, 1024>>>(x);
    k_mask<<<dim3(HWD / 32, CD / 32, NB), dim3(8, 32)>>>(x, out);
}

// round 8
// speedup vs baseline: 1.2435x; 1.1017x over previous
#include <cuda_runtime.h>

#define NB    32
#define HWD   3136
#define CD    256
#define DIM   802816          // 56*56*256
#define KSEL  160564u         // ceil(0.2 * 802816)
#define CUTF  0.70f           // conservative cut; P(x>=0.70)~0.242 >> 0.20003; fb guard covers misses

// ---------------- static device scratch ----------------
__device__ unsigned int g_cnt[NB];
__device__ unsigned int g_h1[NB][2048];       // bits [31:21] histogram (from candidates)
__device__ unsigned int g_h1fb[NB][2048];     // bits [31:21] histogram (fallback, f2u over all)
__device__ unsigned int g_h2[NB][2048];       // bits [20:10] among b1-matching
__device__ unsigned int g_h3[NB][1024];       // bits [9:0]  among (b1,b2)-matching
__device__ unsigned int g_b1[NB], g_kr1[NB];
__device__ unsigned int g_b2[NB], g_kr2[NB];
__device__ unsigned int g_thresh[NB];
__device__ unsigned int g_scratch[NB][DIM];   // candidate buffer

__device__ __forceinline__ unsigned int f2u(float f) {
    unsigned int b = __float_as_uint(f);
    return b ^ (((int)b >> 31) | 0x80000000u);
}

// shfl-based inclusive scan over 1024 threads (2 barriers)
__device__ __forceinline__ unsigned int blockscan1024(unsigned int s, unsigned int* s_warp,
                                                      int lane, int wid) {
    unsigned int incl = s;
    #pragma unroll
    for (int o = 1; o < 32; o <<= 1) {
        unsigned int p = __shfl_up_sync(0xffffffffu, incl, o);
        if (lane >= o) incl += p;
    }
    if (lane == 31) s_warp[wid] = incl;
    __syncthreads();
    if (wid == 0) {
        unsigned int w = s_warp[lane];
        #pragma unroll
        for (int o = 1; o < 32; o <<= 1) {
            unsigned int p = __shfl_up_sync(0xffffffffu, w, o);
            if (lane >= o) w += p;
        }
        s_warp[lane] = w;
    }
    __syncthreads();
    return incl + (wid ? s_warp[wid - 1] : 0u);
}

// ---------------- zero all counters/histograms ----------------
__global__ void k_zero() {
    int i = blockIdx.x * blockDim.x + threadIdx.x;   // 64*1024 = 65536 = NB*2048
    ((unsigned int*)g_h1)[i] = 0u;
    ((unsigned int*)g_h1fb)[i] = 0u;
    ((unsigned int*)g_h2)[i] = 0u;
    if (i < NB * 1024) ((unsigned int*)g_h3)[i] = 0u;
    if (i < NB) g_cnt[i] = 0u;
}

// ---------------- single pass: cut compaction + fused round-1 histogram ----------------
__global__ void k_compact_cut(const float* __restrict__ x) {
    __shared__ unsigned int s_buf[4096];
    __shared__ unsigned int s_h[2048];
    __shared__ unsigned int s_w[8], s_woff[8], s_base, s_tot;
    int b = blockIdx.y;
    int t = threadIdx.x, lane = t & 31, wid = t >> 5;
    const float4* xp = (const float4*)(x + (size_t)b * DIM) + (size_t)blockIdx.x * 1024;

    for (int i = t; i < 2048; i += 256) s_h[i] = 0u;

    float4 v0 = xp[t], v1 = xp[t + 256], v2 = xp[t + 512], v3 = xp[t + 768];
    float f[16] = {v0.x, v0.y, v0.z, v0.w, v1.x, v1.y, v1.z, v1.w,
                   v2.x, v2.y, v2.z, v2.w, v3.x, v3.y, v3.z, v3.w};

    unsigned int c = 0;
    #pragma unroll
    for (int j = 0; j < 16; j++) c += (f[j] >= CUTF);

    unsigned int incl = c;
    #pragma unroll
    for (int o = 1; o < 32; o <<= 1) {
        unsigned int p = __shfl_up_sync(0xffffffffu, incl, o);
        if (lane >= o) incl += p;
    }
    if (lane == 31) s_w[wid] = incl;
    __syncthreads();
    if (t == 0) {
        unsigned int run = 0;
        #pragma unroll
        for (int w = 0; w < 8; w++) { s_woff[w] = run; run += s_w[w]; }
        s_tot = run;
        s_base = run ? atomicAdd(&g_cnt[b], run) : 0u;
    }
    __syncthreads();

    unsigned int idx = s_woff[wid] + (incl - c);
    #pragma unroll
    for (int j = 0; j < 16; j++)
        if (f[j] >= CUTF) {
            unsigned int u = __float_as_uint(f[j]);   // positive: raw bits monotonic
            s_buf[idx++] = u;
            atomicAdd(&s_h[u >> 21], 1u);             // fused round-1 histogram
        }
    __syncthreads();

    unsigned int tot = s_tot, base = s_base;
    unsigned int* dst = g_scratch[b];
    for (unsigned int i = t; i < tot; i += 256) dst[base + i] = s_buf[i];
    for (int i = t; i < 2048; i += 256) {
        unsigned int hc = s_h[i];
        if (hc) atomicAdd(&g_h1[b][i], hc);
    }
}

// ---------------- fallback histogram (early-exits when cut sufficed) ----------------
__global__ void k_fb_hist(const float* __restrict__ x) {
    __shared__ unsigned int h[2048];
    int b = blockIdx.y, t = threadIdx.x;
    if (g_cnt[b] >= KSEL) return;
    for (int i = t; i < 2048; i += 256) h[i] = 0u;
    __syncthreads();
    const float4* xp = (const float4*)(x + (size_t)b * DIM + (size_t)blockIdx.x * (DIM / 8));
    for (unsigned int i = t; i < DIM / 32; i += 256) {
        float4 v = xp[i];
        atomicAdd(&h[f2u(v.x) >> 21], 1u);
        atomicAdd(&h[f2u(v.y) >> 21], 1u);
        atomicAdd(&h[f2u(v.z) >> 21], 1u);
        atomicAdd(&h[f2u(v.w) >> 21], 1u);
    }
    __syncthreads();
    for (int i = t; i < 2048; i += 256) {
        unsigned int c = h[i];
        if (c) atomicAdd(&g_h1fb[b][i], c);
    }
}

// ---------------- scan 2048-bin histogram descending -> bin + residual rank ----------------
__device__ __forceinline__ void scan2048_desc(const unsigned int* H, unsigned int kr,
                                              unsigned int* out_bin, unsigned int* out_kr,
                                              unsigned int* s_warp, unsigned int* s_res) {
    int t = threadIdx.x, lane = t & 31, wid = t >> 5;
    unsigned int loc0 = H[2047 - 2 * t], loc1 = H[2046 - 2 * t];
    unsigned int s = loc0 + loc1;
    unsigned int incl = blockscan1024(s, s_warp, lane, wid);
    unsigned int excl = incl - s;
    if (excl < kr && incl >= kr) {
        if (excl + loc0 >= kr) { s_res[0] = 2047 - 2 * t; s_res[1] = kr - excl; }
        else                   { s_res[0] = 2046 - 2 * t; s_res[1] = kr - excl - loc0; }
    }
    __syncthreads();
    *out_bin = s_res[0];
    *out_kr = s_res[1];
}

__global__ void k_sel_scan1() {
    __shared__ unsigned int s_warp[32], s_res[2];
    int b = blockIdx.x;
    bool fb = (g_cnt[b] < KSEL);
    const unsigned int* H = fb ? g_h1fb[b] : g_h1[b];
    unsigned int bin, kr;
    scan2048_desc(H, KSEL, &bin, &kr, s_warp, s_res);
    if (threadIdx.x == 0) { g_b1[b] = bin; g_kr1[b] = kr; }
}

// ---------------- round-2 histogram: bits [20:10] among b1-matching ----------------
__global__ void k_sel_hist2(const float* __restrict__ x) {
    __shared__ unsigned int h[2048];
    int b = blockIdx.y, t = threadIdx.x;
    for (int i = t; i < 2048; i += 256) h[i] = 0u;
    __syncthreads();
    unsigned int n = g_cnt[b];
    bool fb = (n < KSEL);
    unsigned int b1 = g_b1[b];
    if (!fb) {
        const unsigned int* sp = g_scratch[b];
        unsigned int slice = ((n + 31u) >> 5) << 2;
        unsigned int s0 = blockIdx.x * slice;
        unsigned int s1 = min(s0 + slice, n);
        unsigned int i = s0 + 4u * t;
        for (; i + 3u < s1; i += 1024u) {
            uint4 u = *(const uint4*)(sp + i);
            if ((u.x >> 21) == b1) atomicAdd(&h[(u.x >> 10) & 2047u], 1u);
            if ((u.y >> 21) == b1) atomicAdd(&h[(u.y >> 10) & 2047u], 1u);
            if ((u.z >> 21) == b1) atomicAdd(&h[(u.z >> 10) & 2047u], 1u);
            if ((u.w >> 21) == b1) atomicAdd(&h[(u.w >> 10) & 2047u], 1u);
        }
        for (; i < s1; i++) {
            unsigned int u = sp[i];
            if ((u >> 21) == b1) atomicAdd(&h[(u >> 10) & 2047u], 1u);
        }
    } else {
        const float4* xp = (const float4*)(x + (size_t)b * DIM + (size_t)blockIdx.x * (DIM / 8));
        for (unsigned int i = t; i < DIM / 32; i += 256) {
            float4 v = xp[i];
            unsigned int u0 = f2u(v.x), u1 = f2u(v.y), u2 = f2u(v.z), u3 = f2u(v.w);
            if ((u0 >> 21) == b1) atomicAdd(&h[(u0 >> 10) & 2047u], 1u);
            if ((u1 >> 21) == b1) atomicAdd(&h[(u1 >> 10) & 2047u], 1u);
            if ((u2 >> 21) == b1) atomicAdd(&h[(u2 >> 10) & 2047u], 1u);
            if ((u3 >> 21) == b1) atomicAdd(&h[(u3 >> 10) & 2047u], 1u);
        }
    }
    __syncthreads();
    for (int i = t; i < 2048; i += 256) {
        unsigned int c = h[i];
        if (c) atomicAdd(&g_h2[b][i], c);
    }
}

__global__ void k_sel_scan2() {
    __shared__ unsigned int s_warp[32], s_res[2];
    int b = blockIdx.x;
    unsigned int bin, kr;
    scan2048_desc(g_h2[b], g_kr1[b], &bin, &kr, s_warp, s_res);
    if (threadIdx.x == 0) { g_b2[b] = bin; g_kr2[b] = kr; }
}

// ---------------- round-3 histogram: bits [9:0] among (b1,b2)-matching ----------------
__global__ void k_sel_hist3(const float* __restrict__ x) {
    __shared__ unsigned int h[1024];
    int b = blockIdx.y, t = threadIdx.x;
    for (int i = t; i < 1024; i += 256) h[i] = 0u;
    __syncthreads();
    unsigned int n = g_cnt[b];
    bool fb = (n < KSEL);
    unsigned int top = (g_b1[b] << 11) | g_b2[b];
    if (!fb) {
        const unsigned int* sp = g_scratch[b];
        unsigned int slice = ((n + 31u) >> 5) << 2;
        unsigned int s0 = blockIdx.x * slice;
        unsigned int s1 = min(s0 + slice, n);
        unsigned int i = s0 + 4u * t;
        for (; i + 3u < s1; i += 1024u) {
            uint4 u = *(const uint4*)(sp + i);
            if ((u.x >> 10) == top) atomicAdd(&h[u.x & 1023u], 1u);
            if ((u.y >> 10) == top) atomicAdd(&h[u.y & 1023u], 1u);
            if ((u.z >> 10) == top) atomicAdd(&h[u.z & 1023u], 1u);
            if ((u.w >> 10) == top) atomicAdd(&h[u.w & 1023u], 1u);
        }
        for (; i < s1; i++) {
            unsigned int u = sp[i];
            if ((u >> 10) == top) atomicAdd(&h[u & 1023u], 1u);
        }
    } else {
        const float4* xp = (const float4*)(x + (size_t)b * DIM + (size_t)blockIdx.x * (DIM / 8));
        for (unsigned int i = t; i < DIM / 32; i += 256) {
            float4 v = xp[i];
            unsigned int u0 = f2u(v.x), u1 = f2u(v.y), u2 = f2u(v.z), u3 = f2u(v.w);
            if ((u0 >> 10) == top) atomicAdd(&h[u0 & 1023u], 1u);
            if ((u1 >> 10) == top) atomicAdd(&h[u1 & 1023u], 1u);
            if ((u2 >> 10) == top) atomicAdd(&h[u2 & 1023u], 1u);
            if ((u3 >> 10) == top) atomicAdd(&h[u3 & 1023u], 1u);
        }
    }
    __syncthreads();
    for (int i = t; i < 1024; i += 256) {
        unsigned int c = h[i];
        if (c) atomicAdd(&g_h3[b][i], c);
    }
}

__global__ void k_sel_scan3() {
    __shared__ unsigned int s_warp[32];
    int b = blockIdx.x, t = threadIdx.x;
    int lane = t & 31, wid = t >> 5;
    unsigned int kr = g_kr2[b];
    unsigned int s = g_h3[b][1023 - t];
    unsigned int incl = blockscan1024(s, s_warp, lane, wid);
    unsigned int excl = incl - s;
    if (excl < kr && incl >= kr)
        g_thresh[b] = (g_b1[b] << 21) | (g_b2[b] << 10) | (unsigned int)(1023 - t);
}

// ---------------- threshold + NHWC->NCHW-flatten transpose (128-bit both sides) ----------------
__global__ void k_mask(const float* __restrict__ x, float* __restrict__ out) {
    __shared__ float tile[32][33];
    int b = blockIdx.z;
    unsigned int uth = g_thresh[b];
    bool fb = (g_cnt[b] < KSEL);
    float tf = __uint_as_float(uth);
    const float* xb = x + (size_t)b * DIM;
    float* ob = out + (size_t)b * DIM;
    int hw0 = blockIdx.x * 32;
    int c0  = blockIdx.y * 32;
    int tx = threadIdx.x;                  // 0..7
    int ty = threadIdx.y;                  // 0..31

    float4 v = *(const float4*)(xb + (size_t)(hw0 + ty) * CD + (c0 + 4 * tx));
    float r[4] = {v.x, v.y, v.z, v.w};
    #pragma unroll
    for (int q = 0; q < 4; q++) {
        bool keep = fb ? (f2u(r[q]) >= uth) : (r[q] >= tf);
        tile[4 * tx + q][ty] = keep ? r[q] : 0.0f;
    }
    __syncthreads();

    float4 w;
    w.x = tile[ty][4 * tx];
    w.y = tile[ty][4 * tx + 1];
    w.z = tile[ty][4 * tx + 2];
    w.w = tile[ty][4 * tx + 3];
    *(float4*)(ob + (size_t)(c0 + ty) * HWD + (hw0 + 4 * tx)) = w;
}

// ---------------- launch ----------------
extern "C" void kernel_launch(void* const* d_in, const int* in_sizes, int n_in,
                              void* d_out, int out_size) {
    const float* x = (const float*)d_in[0];
    float* out = (float*)d_out;

    k_zero<<<64, 1024>>>();
    k_compact_cut<<<dim3(196, NB), 256>>>(x);      // 196*4096 = 802816 exactly
    k_fb_hist<<<dim3(8, NB), 256>>>(x);
    k_sel_scan1<<<NB, 1024>>>();
    k_sel_hist2<<<dim3(8, NB), 256>>>(x);
    k_sel_scan2<<<NB, 1024>>>();
    k_sel_hist3<<<dim3(8, NB), 256>>>(x);
    k_sel_scan3<<<NB, 1024>>>();
    k_mask<<<dim3(HWD / 32, CD / 32, NB), dim3(8, 32)>>>(x, out);
}